// round 14
// baseline (speedup 1.0000x reference)
#include <cuda_runtime.h>
#include <math.h>
#include <stdint.h>

#define N_NODES 10000
#define NODES_PAD 10112              // 79 * 128
#define HID 128
#define EDIM 416
#define N_EDGES 160000
#define X_OUT_ELEMS (N_NODES*HID)

// -------- scratch (device globals; no allocations allowed) --------
__device__ __align__(128) float    g_xh[NODES_PAD*HID];
__device__ __align__(128) uint32_t g_m_bf[N_EDGES*64];   // bf16x2-packed m_ij rows
__device__ __align__(128) uint32_t g_w_bf[(size_t)N_EDGES*224]; // bf16x2 weight, 224 words (448 cols, pad 0)
__device__ __align__(128) float    g_agg[NODES_PAD*HID];
__device__ __align__(128) float    g_n1[NODES_PAD*HID];
__device__ __align__(128) float    g_P[NODES_PAD*256];   // [xh@Wi | xh@Wj]
// pre-transposed weights
__device__ __align__(128) float    g_WijT[256*128];
__device__ __align__(128) uint32_t g_WwT_bf[128*224];    // We1 weight-part^T, bf16x2, padded
__device__ __align__(128) uint32_t g_We2T_bf[128*64];
__device__ __align__(128) uint32_t g_WoT_bf[512*64];     // rows 416..511 zero
__device__ __align__(128) float    g_WnT1[128*256];
__device__ __align__(128) float    g_Wn2T[128*128];
// CSR (g_deg zero at load; re-zeroed by agg_kernel each run)
__device__ int g_deg[10016];
__device__ int g_off[10017];
__device__ int g_cur[10016];
__device__ int g_elist[N_EDGES];

__device__ __forceinline__ float silu_f(float x){ return x / (1.0f + __expf(-x)); }
__device__ __forceinline__ uint32_t smem_u32(const void* p){
    uint32_t a;
    asm("{ .reg .u64 t; cvta.to.shared.u64 t, %1; cvt.u32.u64 %0, t; }" : "=r"(a) : "l"(p));
    return a;
}
__device__ __forceinline__ uint32_t packbf(float lo, float hi){
    uint32_t r; asm("cvt.rn.bf16x2.f32 %0, %1, %2;" : "=r"(r) : "f"(hi), "f"(lo)); return r;
}
__device__ __forceinline__ float bflo(uint32_t w){ return __uint_as_float(w << 16); }
__device__ __forceinline__ float bfhi(uint32_t w){ return __uint_as_float(w & 0xFFFF0000u); }

__device__ __forceinline__ void mma8(float* c, const uint32_t* a, uint32_t b0, uint32_t b1){
    asm volatile("mma.sync.aligned.m16n8k8.row.col.f32.tf32.tf32.f32 "
        "{%0,%1,%2,%3}, {%4,%5,%6,%7}, {%8,%9}, {%0,%1,%2,%3};"
        : "+f"(c[0]), "+f"(c[1]), "+f"(c[2]), "+f"(c[3])
        : "r"(a[0]), "r"(a[1]), "r"(a[2]), "r"(a[3]), "r"(b0), "r"(b1));
}
__device__ __forceinline__ void mma16(float* c, const uint32_t* a, uint32_t b0, uint32_t b1){
    asm volatile("mma.sync.aligned.m16n8k16.row.col.f32.bf16.bf16.f32 "
        "{%0,%1,%2,%3}, {%4,%5,%6,%7}, {%8,%9}, {%0,%1,%2,%3};"
        : "+f"(c[0]), "+f"(c[1]), "+f"(c[2]), "+f"(c[3])
        : "r"(a[0]), "r"(a[1]), "r"(a[2]), "r"(a[3]), "r"(b0), "r"(b1));
}
#define CP_ASYNC16(dst, src) \
    asm volatile("cp.async.cg.shared.global [%0], [%1], 16;" :: "r"(dst), "l"(src) : "memory")
#define CP_COMMIT() asm volatile("cp.async.commit_group;" ::: "memory")
#define CP_WAIT(n)  asm volatile("cp.async.wait_group %0;" :: "n"(n) : "memory")

__device__ __forceinline__ int swzi(int r, int k){
    return r*32 + ((((k >> 2) ^ r) & 7) << 2) + (k & 3);
}
#define STG_WORDS  4096
#define NSTAGE     3
#define OFF_A(st)  ((st)*STG_WORDS)
#define OFF_B(st)  (NSTAGE*STG_WORDS + (st)*STG_WORDS)
#define SMEM_STD   (2*NSTAGE*STG_WORDS*4)          // 96KB (tf32 3-stage kernels)
#define SMEM_BF    (4*STG_WORDS*4)                 // 64KB (edge_out)
#define SMEM_FUSED (6*STG_WORDS*4)                 // 96KB (A0 A1 B0 B1 M1a M1b)

// ================= weight conversion (side stream, forked at start) =================
__global__ void conv_w_kernel(const float* __restrict__ w){
    size_t i = (size_t)blockIdx.x*blockDim.x + threadIdx.x;
    if (i < (size_t)N_EDGES*104){          // 104 uint2 (= 416 floats) per row
        size_t e = i/104; int c = (int)(i%104);
        float4 v = *(const float4*)(w + e*416 + c*4);
        uint2 o; o.x = packbf(v.x, v.y); o.y = packbf(v.z, v.w);
        *(uint2*)(g_w_bf + e*224 + c*2) = o;
    }
    if (i < (size_t)N_EDGES*8){            // zero-pad words 208..223
        size_t e = i/8; int c = (int)(i%8);
        *(uint2*)(g_w_bf + e*224 + 208 + c*2) = make_uint2(0u, 0u);
    }
}

// ================= setup =================
__global__ void setup_kernel(const float* __restrict__ We1, const float* __restrict__ We2,
                             const float* __restrict__ Wo,  const float* __restrict__ Wn1,
                             const float* __restrict__ Wn2){
    int i = blockIdx.x*blockDim.x + threadIdx.x;   // grid covers 65536
    if (i < 256*128){ int n = i/128, k = i%128;
        g_WijT[i] = (n < 128) ? We1[k*128 + n] : We1[(128 + k)*128 + (n - 128)]; }
    if (i < 128*224){ int n = i/224, kw = i%224;
        g_WwT_bf[i] = (kw < 208) ? packbf(We1[(256 + 2*kw)*128 + n], We1[(256 + 2*kw + 1)*128 + n]) : 0u; }
    if (i < 128*64){ int n = i/64, kw = i%64;
        g_We2T_bf[i] = packbf(We2[(2*kw)*128 + n], We2[(2*kw+1)*128 + n]); }
    if (i < 512*64){ int n = i/64, kw = i%64;
        g_WoT_bf[i] = (n < EDIM) ? packbf(Wo[(2*kw)*EDIM + n], Wo[(2*kw+1)*EDIM + n]) : 0u; }
    if (i < 128*256){ int n = i/256, k = i%256; g_WnT1[i] = Wn1[k*128 + n]; }
    if (i < 128*128){ int n = i/128, k = i%128; g_Wn2T[i] = Wn2[k*128 + n]; }
}

// -------- layernorm --------
__global__ void ln_kernel(const float* __restrict__ x,
                          const float* __restrict__ g,
                          const float* __restrict__ b){
    int row = blockIdx.x*8 + threadIdx.y;
    if (row >= N_NODES) return;
    int lane = threadIdx.x;
    float4 v = ((const float4*)(x + row*HID))[lane];
    float s = v.x + v.y + v.z + v.w;
    #pragma unroll
    for (int o = 16; o > 0; o >>= 1) s += __shfl_xor_sync(0xffffffffu, s, o);
    float mu = s * (1.0f/HID);
    float dx = v.x-mu, dy = v.y-mu, dz = v.z-mu, dw = v.w-mu;
    float q = dx*dx + dy*dy + dz*dz + dw*dw;
    #pragma unroll
    for (int o = 16; o > 0; o >>= 1) q += __shfl_xor_sync(0xffffffffu, q, o);
    float rstd = rsqrtf(q*(1.0f/HID) + 1e-5f);
    float4 gg = ((const float4*)g)[lane];
    float4 bb = ((const float4*)b)[lane];
    float4 o4;
    o4.x = dx*rstd*gg.x + bb.x;
    o4.y = dy*rstd*gg.y + bb.y;
    o4.z = dz*rstd*gg.z + bb.z;
    o4.w = dw*rstd*gg.w + bb.w;
    ((float4*)(g_xh + row*HID))[lane] = o4;
}

// ================= CSR build (side stream) =================
__global__ void hist_kernel(const int* __restrict__ ei){
    int e = blockIdx.x*blockDim.x + threadIdx.x;
    if (e < N_EDGES) atomicAdd(&g_deg[ei[e]], 1);
}
__global__ void __launch_bounds__(1024) scan_kernel(){
    __shared__ int warp_sums[32];
    int t = threadIdx.x;
    int base = t*10;
    int loc[10];
    int sum = 0;
    #pragma unroll
    for (int j = 0; j < 10; j++){
        int i = base + j;
        int v = (i < 10016) ? g_deg[i] : 0;
        loc[j] = sum; sum += v;
    }
    int lane = t & 31, w = t >> 5;
    int incl = sum;
    #pragma unroll
    for (int o = 1; o < 32; o <<= 1){
        int v = __shfl_up_sync(0xffffffffu, incl, o);
        if (lane >= o) incl += v;
    }
    if (lane == 31) warp_sums[w] = incl;
    __syncthreads();
    if (w == 0){
        int ws = warp_sums[lane];
        #pragma unroll
        for (int o = 1; o < 32; o <<= 1){
            int v = __shfl_up_sync(0xffffffffu, ws, o);
            if (lane >= o) ws += v;
        }
        warp_sums[lane] = ws;
    }
    __syncthreads();
    int offset = incl - sum + ((w > 0) ? warp_sums[w-1] : 0);
    #pragma unroll
    for (int j = 0; j < 10; j++){
        int i = base + j;
        if (i < 10016){ int o = offset + loc[j]; g_off[i] = o; g_cur[i] = o; }
    }
    if (t == 1023) g_off[10016] = offset + sum;
}
__global__ void scatter_kernel(const int* __restrict__ ei){
    int e = blockIdx.x*blockDim.x + threadIdx.x;
    if (e < N_EDGES){
        int n = ei[e];
        int p = atomicAdd(&g_cur[n], 1);
        g_elist[p] = e;
    }
}
__global__ void __launch_bounds__(1024) agg_kernel(){
    int z = blockIdx.x*blockDim.x + threadIdx.x;
    if (z < 10016) g_deg[z] = 0;
    int wid = threadIdx.x >> 5, lane = threadIdx.x & 31;
    int n = blockIdx.x*32 + wid;
    if (n >= N_NODES) return;
    int o0 = g_off[n], o1 = g_off[n+1];
    float4 acc = make_float4(0.f, 0.f, 0.f, 0.f);
    for (int i = o0; i < o1; i++){
        int e0 = g_elist[i];
        uint2 w = *(const uint2*)(g_m_bf + (size_t)e0*64 + lane*2);
        acc.x += bflo(w.x); acc.y += bfhi(w.x);
        acc.z += bflo(w.y); acc.w += bfhi(w.y);
    }
    int deg = o1 - o0;
    float s = (deg > 0) ? 1.0f/(float)deg : 1.0f;
    float4 o;
    o.x = acc.x*s; o.y = acc.y*s; o.z = acc.z*s; o.w = acc.w*s;
    *(float4*)(g_agg + (size_t)n*HID + lane*4) = o;
}

// ============ MMA core: 128x128 tile, 8 warps (2x4), warp tile 64x32 ============
#define MMA_TILE_G(tA, tB, MMAOP) do { \
    _Pragma("unroll") \
    for (int k0 = 0; k0 < 32; k0 += 8){ \
        uint32_t a[4][4]; \
        _Pragma("unroll") \
        for (int mt = 0; mt < 4; mt++){ \
            int R0 = wm + mt*16 + lr; \
            a[mt][0] = (tA)[swzi(R0,     k0 + lc)]; \
            a[mt][1] = (tA)[swzi(R0 + 8, k0 + lc)]; \
            a[mt][2] = (tA)[swzi(R0,     k0 + 4 + lc)]; \
            a[mt][3] = (tA)[swzi(R0 + 8, k0 + 4 + lc)]; \
        } \
        _Pragma("unroll") \
        for (int nt = 0; nt < 4; nt++){ \
            int n = wn + nt*8 + lr; \
            uint32_t b0 = (tB)[swzi(n, k0 + lc)]; \
            uint32_t b1 = (tB)[swzi(n, k0 + 4 + lc)]; \
            _Pragma("unroll") \
            for (int mt = 0; mt < 4; mt++) MMAOP(acc[mt][nt], a[mt], b0, b1); \
        } \
    } \
} while(0)
#define ACC_ZERO4() do { \
    _Pragma("unroll") \
    for (int i = 0; i < 4; i++) \
        _Pragma("unroll") \
        for (int j = 0; j < 4; j++){ acc[i][j][0]=0; acc[i][j][1]=0; acc[i][j][2]=0; acc[i][j][3]=0; } \
} while(0)

// -------- pre: P = xh @ [Wi | Wj]  (grid: 79 x 2, tf32) --------
__global__ void __launch_bounds__(256, 2) pre_P_mma(){
    extern __shared__ uint32_t dynsm[];
    const int tid = threadIdx.x;
    const int r0  = blockIdx.x*128;
    const int nb  = blockIdx.y;
    const uint32_t sbase = smem_u32(dynsm);
    const int lane = tid & 31, lr = lane >> 2, lc = lane & 3;
    const int wid = tid >> 5;
    const int wm = (wid & 1)*64, wn = (wid >> 1)*32;
    float acc[4][4][4];
    ACC_ZERO4();
    const int lr8 = tid >> 3, lc8 = tid & 7;

    #define ISSUE_P(st, kt) do { \
        uint32_t ab = sbase + OFF_A(st)*4u; \
        uint32_t bb = sbase + OFF_B(st)*4u; \
        _Pragma("unroll") \
        for (int i = 0; i < 4; i++){ \
            int r = lr8 + i*32, c = lc8; \
            int kg = (kt) + c*4; \
            uint32_t off = (uint32_t)(r*32 + (((c ^ r) & 7) << 2))*4u; \
            CP_ASYNC16(ab + off, (const void*)(g_xh + (size_t)(r0 + r)*HID + kg)); \
            CP_ASYNC16(bb + off, (const void*)(g_WijT + (size_t)(nb*128 + r)*HID + kg)); \
        } \
        CP_COMMIT(); \
    } while(0)

    ISSUE_P(0, 0);
    ISSUE_P(1, 32);
    int st = 0;
    for (int t = 0; t < 4; t++){
        if (t + 1 < 4) CP_WAIT(1); else CP_WAIT(0);
        __syncthreads();
        if (t + 2 < 4){
            int s2 = st + 2; if (s2 >= NSTAGE) s2 -= NSTAGE;
            ISSUE_P(s2, (t+2)*32);
        }
        MMA_TILE_G(dynsm + OFF_A(st), dynsm + OFF_B(st), mma8);
        if (++st == NSTAGE) st = 0;
    }
    #undef ISSUE_P
    #pragma unroll
    for (int mt = 0; mt < 4; mt++){
        int r1 = r0 + wm + mt*16 + lr;
        #pragma unroll
        for (int nt = 0; nt < 4; nt++){
            int c = wn + nt*8 + lc*2;
            float2 v1, v2;
            v1.x = acc[mt][nt][0]; v1.y = acc[mt][nt][1];
            v2.x = acc[mt][nt][2]; v2.y = acc[mt][nt][3];
            *(float2*)(g_P + (size_t)r1*256 + nb*128 + c) = v1;
            *(float2*)(g_P + (size_t)(r1+8)*256 + nb*128 + c) = v2;
        }
    }
}

// -------- FUSED edge kernel: phase A (w@Ww + P gathers, bf16) -> m1 in smem;
//          phase B (m1@We2, attention, gating) -> g_m_bf --------
__global__ void __launch_bounds__(256, 2) edge_fused_mma(const float* __restrict__ be1,
                                                         const float* __restrict__ be2,
                                                         const float* __restrict__ Wa,
                                                         const float* __restrict__ ba,
                                                         const int* __restrict__ ei){
    extern __shared__ uint32_t dynsm[];   // A0 A1 B0 B1 M1a M1b (4096 words each)
    __shared__ float sB1[128], sB2[128], sWa[128], s_att[128];
    __shared__ int s_ii[128], s_jj[128];
    const int tid = threadIdx.x;
    const int e0  = blockIdx.x*128;
    if (tid < 128){
        s_ii[tid] = ei[e0 + tid];
        s_jj[tid] = ei[N_EDGES + e0 + tid];
        sB1[tid] = be1[tid];
        sB2[tid] = be2[tid];
        sWa[tid] = Wa[tid];
        s_att[tid] = 0.0f;
    }
    __syncthreads();
    const uint32_t sbase = smem_u32(dynsm);
    const int lane = tid & 31, lr = lane >> 2, lc = lane & 3;
    const int wid = tid >> 5;
    const int wm = (wid & 1)*64, wn = (wid >> 1)*32;
    float acc[4][4][4];
    ACC_ZERO4();
    const int lr8 = tid >> 3, lc8 = tid & 7;

    // ---- phase A: 7 bf16 K-tiles (448 padded cols), 2-stage ----
    #define ISSUE_F(st, t) do { \
        uint32_t ab = sbase + (st)*(STG_WORDS*4u); \
        uint32_t bb = sbase + (2 + (st))*(STG_WORDS*4u); \
        _Pragma("unroll") \
        for (int i = 0; i < 4; i++){ \
            int r = lr8 + i*32, c = lc8; \
            uint32_t off = (uint32_t)(r*32 + (((c ^ r) & 7) << 2))*4u; \
            CP_ASYNC16(ab + off, (const void*)(g_w_bf + (size_t)(e0 + r)*224 + (t)*32 + c*4)); \
            CP_ASYNC16(bb + off, (const void*)(g_WwT_bf + (size_t)r*224 + (t)*32 + c*4)); \
        } \
        CP_COMMIT(); \
    } while(0)

    ISSUE_F(0, 0);
    for (int t = 0; t < 7; t++){
        CP_WAIT(0);
        __syncthreads();
        if (t + 1 < 7) ISSUE_F((t+1)&1, t+1);
        MMA_TILE_G(dynsm + (t&1)*STG_WORDS, dynsm + (2 + (t&1))*STG_WORDS, mma16);
    }
    #undef ISSUE_F
    __syncthreads();   // all warps done with A/B stage buffers

    // stage We2 (bf16, 2 tiles) into B0/B1 while computing the phase-A epilogue
    #pragma unroll
    for (int tt = 0; tt < 2; tt++){
        #pragma unroll
        for (int i = 0; i < 4; i++){
            int r = lr8 + i*32, c = lc8;
            uint32_t off = (uint32_t)(r*32 + (((c ^ r) & 7) << 2))*4u;
            CP_ASYNC16(sbase + (2 + tt)*(STG_WORDS*4u) + off,
                       (const void*)(g_We2T_bf + (size_t)r*64 + tt*32 + c*4));
        }
    }
    CP_COMMIT();

    // phase-A epilogue: m1 = silu(acc + P_i + P_j + be1) -> M1 smem (bf16x2, swizzled)
    #pragma unroll
    for (int mt = 0; mt < 4; mt++){
        int r1 = wm + mt*16 + lr, r2 = r1 + 8;
        const float* P1i = g_P + (size_t)s_ii[r1]*256;
        const float* P1j = g_P + (size_t)s_jj[r1]*256 + 128;
        const float* P2i = g_P + (size_t)s_ii[r2]*256;
        const float* P2j = g_P + (size_t)s_jj[r2]*256 + 128;
        #pragma unroll
        for (int nt = 0; nt < 4; nt++){
            int c = wn + nt*8 + lc*2;
            float2 p1i = *(const float2*)(P1i + c), p1j = *(const float2*)(P1j + c);
            float2 p2i = *(const float2*)(P2i + c), p2j = *(const float2*)(P2j + c);
            float a0 = silu_f(acc[mt][nt][0] + p1i.x + p1j.x + sB1[c]);
            float a1 = silu_f(acc[mt][nt][1] + p1i.y + p1j.y + sB1[c+1]);
            float a2 = silu_f(acc[mt][nt][2] + p2i.x + p2j.x + sB1[c]);
            float a3 = silu_f(acc[mt][nt][3] + p2i.y + p2j.y + sB1[c+1]);
            int kb = c >> 6, kw = (c & 63) >> 1;
            dynsm[(4 + kb)*STG_WORDS + swzi(r1, kw)] = packbf(a0, a1);
            dynsm[(4 + kb)*STG_WORDS + swzi(r2, kw)] = packbf(a2, a3);
        }
    }
    CP_WAIT(0);
    __syncthreads();   // M1 visible + We2 staged

    // ---- phase B: m2 = m1 @ We2 (2 bf16 tiles from smem) ----
    ACC_ZERO4();
    MMA_TILE_G(dynsm + 4*STG_WORDS, dynsm + 2*STG_WORDS, mma16);
    MMA_TILE_G(dynsm + 5*STG_WORDS, dynsm + 3*STG_WORDS, mma16);

    // attention + gating epilogue
    #pragma unroll
    for (int mt = 0; mt < 4; mt++){
        float p0 = 0.0f, p1 = 0.0f;
        #pragma unroll
        for (int nt = 0; nt < 4; nt++){
            int c = wn + nt*8 + lc*2;
            float wa0 = sWa[c], wa1 = sWa[c+1];
            float v0 = silu_f(acc[mt][nt][0] + sB2[c]);
            float v1 = silu_f(acc[mt][nt][1] + sB2[c+1]);
            float v2 = silu_f(acc[mt][nt][2] + sB2[c]);
            float v3 = silu_f(acc[mt][nt][3] + sB2[c+1]);
            acc[mt][nt][0]=v0; acc[mt][nt][1]=v1; acc[mt][nt][2]=v2; acc[mt][nt][3]=v3;
            p0 += v0*wa0 + v1*wa1;
            p1 += v2*wa0 + v3*wa1;
        }
        atomicAdd(&s_att[wm + mt*16 + lr], p0);
        atomicAdd(&s_att[wm + mt*16 + lr + 8], p1);
    }
    __syncthreads();
    const float ba0 = ba[0];
    #pragma unroll
    for (int mt = 0; mt < 4; mt++){
        int r1 = wm + mt*16 + lr, r2 = r1 + 8;
        float att1 = silu_f(s_att[r1] + ba0);
        float att2 = silu_f(s_att[r2] + ba0);
        #pragma unroll
        for (int nt = 0; nt < 4; nt++){
            int c = wn + nt*8 + lc*2;
            g_m_bf[(size_t)(e0 + r1)*64 + (c >> 1)] = packbf(acc[mt][nt][0]*att1, acc[mt][nt][1]*att1);
            g_m_bf[(size_t)(e0 + r2)*64 + (c >> 1)] = packbf(acc[mt][nt][2]*att2, acc[mt][nt][3]*att2);
        }
    }
}

// -------- edge out (bf16): resident A (2 tiles) + 4 N-blocks x 2 K-tiles --------
__global__ void __launch_bounds__(256, 2) edge_out_mma(const float* __restrict__ bo,
                                                       const float* __restrict__ weight,
                                                       float* __restrict__ out){
    extern __shared__ uint32_t dynsm[];
    __shared__ float sBias[512];
    const int tid = threadIdx.x;
    const int e0  = blockIdx.x*128;
    sBias[tid] = (tid < EDIM) ? bo[tid] : 0.0f;
    sBias[tid+256] = (tid+256 < EDIM) ? bo[tid+256] : 0.0f;
    __syncthreads();
    const uint32_t sbase = smem_u32(dynsm);
    const int lane = tid & 31, lr = lane >> 2, lc = lane & 3;
    const int wid = tid >> 5;
    const int wm = (wid & 1)*64, wn = (wid >> 1)*32;
    float acc[4][4][4];
    const int lr8 = tid >> 3, lc8 = tid & 7;

    #pragma unroll
    for (int kb = 0; kb < 2; kb++){
        #pragma unroll
        for (int i = 0; i < 4; i++){
            int r = lr8 + i*32, c = lc8;
            uint32_t off = (uint32_t)(kb*STG_WORDS + r*32 + (((c ^ r) & 7) << 2))*4u;
            CP_ASYNC16(sbase + off, (const void*)(g_m_bf + (size_t)(e0 + r)*64 + kb*32 + c*4));
        }
    }
    CP_COMMIT();

    #define ISSUE_EO(st, idx) do { \
        int nb_ = (idx) >> 1, kt_ = (idx) & 1; \
        uint32_t bb = sbase + (2 + (st))*(STG_WORDS*4u); \
        _Pragma("unroll") \
        for (int i = 0; i < 4; i++){ \
            int r = lr8 + i*32, c = lc8; \
            uint32_t off = (uint32_t)(r*32 + (((c ^ r) & 7) << 2))*4u; \
            CP_ASYNC16(bb + off, (const void*)(g_WoT_bf + (size_t)(nb_*128 + r)*64 + kt_*32 + c*4)); \
        } \
        CP_COMMIT(); \
    } while(0)

    ISSUE_EO(0, 0);
    for (int idx = 0; idx < 8; idx++){
        int nb = idx >> 1, kt = idx & 1;
        if (kt == 0) ACC_ZERO4();
        CP_WAIT(0);
        __syncthreads();
        if (idx + 1 < 8) ISSUE_EO((idx+1)&1, idx+1);
        MMA_TILE_G(dynsm + kt*STG_WORDS, dynsm + (2 + (idx&1))*STG_WORDS, mma16);
        if (kt == 1){
            #pragma unroll
            for (int mt = 0; mt < 4; mt++){
                int r1 = e0 + wm + mt*16 + lr;
                #pragma unroll
                for (int nt = 0; nt < 4; nt++){
                    int c = wn + nt*8 + lc*2;
                    int g = nb*128 + c;
                    if (g < EDIM){
                        float2 w1 = *(const float2*)(weight + (size_t)r1*EDIM + g);
                        float2 w2 = *(const float2*)(weight + (size_t)(r1+8)*EDIM + g);
                        float2 v1, v2;
                        v1.x = w1.x + silu_f(acc[mt][nt][0] + sBias[g]);
                        v1.y = w1.y + silu_f(acc[mt][nt][1] + sBias[g+1]);
                        v2.x = w2.x + silu_f(acc[mt][nt][2] + sBias[g]);
                        v2.y = w2.y + silu_f(acc[mt][nt][3] + sBias[g+1]);
                        *(float2*)(out + X_OUT_ELEMS + (size_t)r1*EDIM + g) = v1;
                        *(float2*)(out + X_OUT_ELEMS + (size_t)(r1+8)*EDIM + g) = v2;
                    }
                }
            }
        }
    }
    #undef ISSUE_EO
}

// -------- node MLP 1 (tf32) --------
__global__ void __launch_bounds__(256, 2) node_mlp1_mma(const float* __restrict__ bn1){
    extern __shared__ uint32_t dynsm[];
    __shared__ float sBias[128];
    const int tid = threadIdx.x;
    const int r0  = blockIdx.x*128;
    if (tid < 128) sBias[tid] = bn1[tid];
    __syncthreads();
    const uint32_t sbase = smem_u32(dynsm);
    const int lane = tid & 31, lr = lane >> 2, lc = lane & 3;
    const int wid = tid >> 5;
    const int wm = (wid & 1)*64, wn = (wid >> 1)*32;
    float acc[4][4][4];
    ACC_ZERO4();
    const int lr8 = tid >> 3, lc8 = tid & 7;

    #define ISSUE_N1(st, kt) do { \
        uint32_t ab = sbase + OFF_A(st)*4u; \
        uint32_t bb = sbase + OFF_B(st)*4u; \
        _Pragma("unroll") \
        for (int i = 0; i < 4; i++){ \
            int r = lr8 + i*32, c = lc8; \
            int kg = (kt) + c*4; \
            const void* srcA = (kg < HID) ? (const void*)(g_xh + (size_t)(r0 + r)*HID + kg) \
                                          : (const void*)(g_agg + (size_t)(r0 + r)*HID + (kg - HID)); \
            uint32_t off = (uint32_t)(r*32 + (((c ^ r) & 7) << 2))*4u; \
            CP_ASYNC16(ab + off, srcA); \
            CP_ASYNC16(bb + off, (const void*)(g_WnT1 + (size_t)r*256 + kg)); \
        } \
        CP_COMMIT(); \
    } while(0)

    ISSUE_N1(0, 0);
    ISSUE_N1(1, 32);
    int st = 0;
    for (int t = 0; t < 8; t++){
        if (t + 1 < 8) CP_WAIT(1); else CP_WAIT(0);
        __syncthreads();
        if (t + 2 < 8){
            int s2 = st + 2; if (s2 >= NSTAGE) s2 -= NSTAGE;
            ISSUE_N1(s2, (t+2)*32);
        }
        MMA_TILE_G(dynsm + OFF_A(st), dynsm + OFF_B(st), mma8);
        if (++st == NSTAGE) st = 0;
    }
    #undef ISSUE_N1
    #pragma unroll
    for (int mt = 0; mt < 4; mt++){
        int r1 = r0 + wm + mt*16 + lr;
        #pragma unroll
        for (int nt = 0; nt < 4; nt++){
            int c = wn + nt*8 + lc*2;
            float2 v1, v2;
            v1.x = silu_f(acc[mt][nt][0] + sBias[c]);
            v1.y = silu_f(acc[mt][nt][1] + sBias[c+1]);
            v2.x = silu_f(acc[mt][nt][2] + sBias[c]);
            v2.y = silu_f(acc[mt][nt][3] + sBias[c+1]);
            *(float2*)(g_n1 + (size_t)r1*HID + c) = v1;
            *(float2*)(g_n1 + (size_t)(r1+8)*HID + c) = v2;
        }
    }
}

// -------- node MLP 2 (tf32) + residual --------
__global__ void __launch_bounds__(256, 2) node_mlp2_mma(const float* __restrict__ bn2,
                                                        float* __restrict__ out){
    extern __shared__ uint32_t dynsm[];
    __shared__ float sBias[128];
    const int tid = threadIdx.x;
    const int r0  = blockIdx.x*128;
    if (tid < 128) sBias[tid] = bn2[tid];
    __syncthreads();
    const uint32_t sbase = smem_u32(dynsm);
    const int lane = tid & 31, lr = lane >> 2, lc = lane & 3;
    const int wid = tid >> 5;
    const int wm = (wid & 1)*64, wn = (wid >> 1)*32;
    float acc[4][4][4];
    ACC_ZERO4();
    const int lr8 = tid >> 3, lc8 = tid & 7;

    #define ISSUE_N2(st, kt) do { \
        uint32_t ab = sbase + OFF_A(st)*4u; \
        uint32_t bb = sbase + OFF_B(st)*4u; \
        _Pragma("unroll") \
        for (int i = 0; i < 4; i++){ \
            int r = lr8 + i*32, c = lc8; \
            int kg = (kt) + c*4; \
            uint32_t off = (uint32_t)(r*32 + (((c ^ r) & 7) << 2))*4u; \
            CP_ASYNC16(ab + off, (const void*)(g_n1 + (size_t)(r0 + r)*HID + kg)); \
            CP_ASYNC16(bb + off, (const void*)(g_Wn2T + (size_t)r*HID + kg)); \
        } \
        CP_COMMIT(); \
    } while(0)

    ISSUE_N2(0, 0);
    ISSUE_N2(1, 32);
    int st = 0;
    for (int t = 0; t < 4; t++){
        if (t + 1 < 4) CP_WAIT(1); else CP_WAIT(0);
        __syncthreads();
        if (t + 2 < 4){
            int s2 = st + 2; if (s2 >= NSTAGE) s2 -= NSTAGE;
            ISSUE_N2(s2, (t+2)*32);
        }
        MMA_TILE_G(dynsm + OFF_A(st), dynsm + OFF_B(st), mma8);
        if (++st == NSTAGE) st = 0;
    }
    #undef ISSUE_N2
    #pragma unroll
    for (int mt = 0; mt < 4; mt++){
        int r1 = r0 + wm + mt*16 + lr;
        #pragma unroll
        for (int nt = 0; nt < 4; nt++){
            int c = wn + nt*8 + lc*2;
            if (r1 < N_NODES){
                float2 xh1 = *(const float2*)(g_xh + (size_t)r1*HID + c);
                float2 v1;
                v1.x = xh1.x + silu_f(acc[mt][nt][0] + sBias[c]);
                v1.y = xh1.y + silu_f(acc[mt][nt][1] + sBias[c+1]);
                *(float2*)(out + (size_t)r1*HID + c) = v1;
            }
            if (r1 + 8 < N_NODES){
                float2 xh2 = *(const float2*)(g_xh + (size_t)(r1+8)*HID + c);
                float2 v2;
                v2.x = xh2.x + silu_f(acc[mt][nt][2] + sBias[c]);
                v2.y = xh2.y + silu_f(acc[mt][nt][3] + sBias[c+1]);
                *(float2*)(out + (size_t)(r1+8)*HID + c) = v2;
            }
        }
    }
}

extern "C" void kernel_launch(void* const* d_in, const int* in_sizes, int n_in,
                              void* d_out, int out_size){
    const float* x    = (const float*)d_in[0];
    const float* wgt  = (const float*)d_in[1];
    const float* ln_g = (const float*)d_in[2];
    const float* ln_b = (const float*)d_in[3];
    const float* We1  = (const float*)d_in[4];
    const float* be1  = (const float*)d_in[5];
    const float* We2  = (const float*)d_in[6];
    const float* be2  = (const float*)d_in[7];
    const float* Wa   = (const float*)d_in[8];
    const float* ba   = (const float*)d_in[9];
    const float* Wn1  = (const float*)d_in[10];
    const float* bn1  = (const float*)d_in[11];
    const float* Wn2  = (const float*)d_in[12];
    const float* bn2  = (const float*)d_in[13];
    const float* Wo   = (const float*)d_in[14];
    const float* bo   = (const float*)d_in[15];
    const int*   ei   = (const int*)d_in[16];
    float* out = (float*)d_out;

    cudaFuncSetAttribute(pre_P_mma,      cudaFuncAttributeMaxDynamicSharedMemorySize, SMEM_STD);
    cudaFuncSetAttribute(edge_fused_mma, cudaFuncAttributeMaxDynamicSharedMemorySize, SMEM_FUSED);
    cudaFuncSetAttribute(edge_out_mma,   cudaFuncAttributeMaxDynamicSharedMemorySize, SMEM_BF);
    cudaFuncSetAttribute(node_mlp1_mma,  cudaFuncAttributeMaxDynamicSharedMemorySize, SMEM_STD);
    cudaFuncSetAttribute(node_mlp2_mma,  cudaFuncAttributeMaxDynamicSharedMemorySize, SMEM_STD);

    cudaStream_t s1;
    cudaStreamCreateWithFlags(&s1, cudaStreamNonBlocking);
    cudaEvent_t evFork, evConv, evM, evJoin;
    cudaEventCreateWithFlags(&evFork, cudaEventDisableTiming);
    cudaEventCreateWithFlags(&evConv, cudaEventDisableTiming);
    cudaEventCreateWithFlags(&evM,    cudaEventDisableTiming);
    cudaEventCreateWithFlags(&evJoin, cudaEventDisableTiming);

    cudaEventRecord(evFork, 0);

    // main chain
    setup_kernel<<<(65536 + 255)/256, 256>>>(We1, We2, Wo, Wn1, Wn2);
    ln_kernel<<<(N_NODES + 7)/8, dim3(32, 8)>>>(x, ln_g, ln_b);
    pre_P_mma<<<dim3(NODES_PAD/128, 2), 256, SMEM_STD>>>();

    // side chain: weight -> bf16 conversion (concurrent with setup/ln/pre_P)
    cudaStreamWaitEvent(s1, evFork, 0);
    conv_w_kernel<<<(int)(((size_t)N_EDGES*104 + 255)/256), 256, 0, s1>>>(wgt);
    cudaEventRecord(evConv, s1);

    // fused edge kernel (needs conv + setup + ln + pre_P)
    cudaStreamWaitEvent(0, evConv, 0);
    edge_fused_mma<<<N_EDGES/128, 256, SMEM_FUSED>>>(be1, be2, Wa, ba, ei);

    // side chain: CSR build (after conv on s1; needed only before agg)
    hist_kernel<<<(N_EDGES + 255)/256, 256, 0, s1>>>(ei);
    scan_kernel<<<1, 1024, 0, s1>>>();
    scatter_kernel<<<(N_EDGES + 255)/256, 256, 0, s1>>>(ei);

    cudaEventRecord(evM, 0);                    // m_ij ready

    // side chain: node pipeline (concurrent with edge_out)
    cudaStreamWaitEvent(s1, evM, 0);
    agg_kernel<<<(N_NODES + 31)/32, 1024, 0, s1>>>();
    node_mlp1_mma<<<NODES_PAD/128, 256, SMEM_STD, s1>>>(bn1);
    node_mlp2_mma<<<NODES_PAD/128, 256, SMEM_STD, s1>>>(bn2, out);
    cudaEventRecord(evJoin, s1);

    // main chain: edge output transform
    edge_out_mma<<<N_EDGES/128, 256, SMEM_BF>>>(bo, wgt, out);
    cudaStreamWaitEvent(0, evJoin, 0);
}

// round 15
// speedup vs baseline: 1.0472x; 1.0472x over previous
#include <cuda_runtime.h>
#include <math.h>
#include <stdint.h>

#define N_NODES 10000
#define NODES_PAD 10112              // 79 * 128
#define HID 128
#define EDIM 416
#define N_EDGES 160000
#define X_OUT_ELEMS (N_NODES*HID)

// -------- scratch (device globals; no allocations allowed) --------
__device__ __align__(128) float    g_xh[NODES_PAD*HID];
__device__ __align__(128) uint32_t g_m_bf[N_EDGES*64];   // bf16x2-packed m_ij rows
__device__ __align__(128) float    g_agg[NODES_PAD*HID];
__device__ __align__(128) float    g_n1[NODES_PAD*HID];
__device__ __align__(128) float    g_P[NODES_PAD*256];   // [xh@Wi | xh@Wj]
// pre-transposed weights
__device__ __align__(128) float    g_WijT[256*128];
__device__ __align__(128) float    g_WwT[128*EDIM];      // We1 weight-part^T (fp32)
__device__ __align__(128) uint32_t g_We2T_bf[128*64];
__device__ __align__(128) uint32_t g_WoT_bf[512*64];     // rows 416..511 zero
__device__ __align__(128) float    g_WnT1[128*256];
__device__ __align__(128) float    g_Wn2T[128*128];
// CSR (g_deg zero at load; re-zeroed by agg_kernel each run)
__device__ int g_deg[10016];
__device__ int g_off[10017];
__device__ int g_cur[10016];
__device__ int g_elist[N_EDGES];

__device__ __forceinline__ float silu_f(float x){ return x / (1.0f + __expf(-x)); }
__device__ __forceinline__ uint32_t smem_u32(const void* p){
    uint32_t a;
    asm("{ .reg .u64 t; cvta.to.shared.u64 t, %1; cvt.u32.u64 %0, t; }" : "=r"(a) : "l"(p));
    return a;
}
__device__ __forceinline__ uint32_t packbf(float lo, float hi){
    uint32_t r; asm("cvt.rn.bf16x2.f32 %0, %1, %2;" : "=r"(r) : "f"(hi), "f"(lo)); return r;
}
__device__ __forceinline__ float bflo(uint32_t w){ return __uint_as_float(w << 16); }
__device__ __forceinline__ float bfhi(uint32_t w){ return __uint_as_float(w & 0xFFFF0000u); }

__device__ __forceinline__ void mma8(float* c, const uint32_t* a, uint32_t b0, uint32_t b1){
    asm volatile("mma.sync.aligned.m16n8k8.row.col.f32.tf32.tf32.f32 "
        "{%0,%1,%2,%3}, {%4,%5,%6,%7}, {%8,%9}, {%0,%1,%2,%3};"
        : "+f"(c[0]), "+f"(c[1]), "+f"(c[2]), "+f"(c[3])
        : "r"(a[0]), "r"(a[1]), "r"(a[2]), "r"(a[3]), "r"(b0), "r"(b1));
}
__device__ __forceinline__ void mma16(float* c, const uint32_t* a, uint32_t b0, uint32_t b1){
    asm volatile("mma.sync.aligned.m16n8k16.row.col.f32.bf16.bf16.f32 "
        "{%0,%1,%2,%3}, {%4,%5,%6,%7}, {%8,%9}, {%0,%1,%2,%3};"
        : "+f"(c[0]), "+f"(c[1]), "+f"(c[2]), "+f"(c[3])
        : "r"(a[0]), "r"(a[1]), "r"(a[2]), "r"(a[3]), "r"(b0), "r"(b1));
}
#define CP_ASYNC16(dst, src) \
    asm volatile("cp.async.cg.shared.global [%0], [%1], 16;" :: "r"(dst), "l"(src) : "memory")
#define CP_COMMIT() asm volatile("cp.async.commit_group;" ::: "memory")
#define CP_WAIT(n)  asm volatile("cp.async.wait_group %0;" :: "n"(n) : "memory")

__device__ __forceinline__ int swzi(int r, int k){
    return r*32 + ((((k >> 2) ^ r) & 7) << 2) + (k & 3);
}
#define STG_WORDS  4096
#define NSTAGE     3
#define OFF_A(st)  ((st)*STG_WORDS)
#define OFF_B(st)  (NSTAGE*STG_WORDS + (st)*STG_WORDS)
#define SMEM_STD   (2*NSTAGE*STG_WORDS*4)          // 96KB (tf32 3-stage kernels)
#define SMEM_BF    (4*STG_WORDS*4)                 // 64KB (edge_out)
#define SMEM_FUSED (6*STG_WORDS*4)                 // 96KB (A0 A1 B0 B1 M1a M1b)

// ================= setup =================
__global__ void setup_kernel(const float* __restrict__ We1, const float* __restrict__ We2,
                             const float* __restrict__ Wo,  const float* __restrict__ Wn1,
                             const float* __restrict__ Wn2){
    int i = blockIdx.x*blockDim.x + threadIdx.x;   // grid covers 65536
    if (i < 256*128){ int n = i/128, k = i%128;
        g_WijT[i] = (n < 128) ? We1[k*128 + n] : We1[(128 + k)*128 + (n - 128)]; }
    if (i < 128*EDIM){ int n = i/EDIM, k = i%EDIM; g_WwT[i] = We1[(256 + k)*128 + n]; }
    if (i < 128*64){ int n = i/64, kw = i%64;
        g_We2T_bf[i] = packbf(We2[(2*kw)*128 + n], We2[(2*kw+1)*128 + n]); }
    if (i < 512*64){ int n = i/64, kw = i%64;
        g_WoT_bf[i] = (n < EDIM) ? packbf(Wo[(2*kw)*EDIM + n], Wo[(2*kw+1)*EDIM + n]) : 0u; }
    if (i < 128*256){ int n = i/256, k = i%256; g_WnT1[i] = Wn1[k*128 + n]; }
    if (i < 128*128){ int n = i/128, k = i%128; g_Wn2T[i] = Wn2[k*128 + n]; }
}

// -------- layernorm --------
__global__ void ln_kernel(const float* __restrict__ x,
                          const float* __restrict__ g,
                          const float* __restrict__ b){
    int row = blockIdx.x*8 + threadIdx.y;
    if (row >= N_NODES) return;
    int lane = threadIdx.x;
    float4 v = ((const float4*)(x + row*HID))[lane];
    float s = v.x + v.y + v.z + v.w;
    #pragma unroll
    for (int o = 16; o > 0; o >>= 1) s += __shfl_xor_sync(0xffffffffu, s, o);
    float mu = s * (1.0f/HID);
    float dx = v.x-mu, dy = v.y-mu, dz = v.z-mu, dw = v.w-mu;
    float q = dx*dx + dy*dy + dz*dz + dw*dw;
    #pragma unroll
    for (int o = 16; o > 0; o >>= 1) q += __shfl_xor_sync(0xffffffffu, q, o);
    float rstd = rsqrtf(q*(1.0f/HID) + 1e-5f);
    float4 gg = ((const float4*)g)[lane];
    float4 bb = ((const float4*)b)[lane];
    float4 o4;
    o4.x = dx*rstd*gg.x + bb.x;
    o4.y = dy*rstd*gg.y + bb.y;
    o4.z = dz*rstd*gg.z + bb.z;
    o4.w = dw*rstd*gg.w + bb.w;
    ((float4*)(g_xh + row*HID))[lane] = o4;
}

// ================= CSR build (side stream) =================
__global__ void hist_kernel(const int* __restrict__ ei){
    int e = blockIdx.x*blockDim.x + threadIdx.x;
    if (e < N_EDGES) atomicAdd(&g_deg[ei[e]], 1);
}
__global__ void __launch_bounds__(1024) scan_kernel(){
    __shared__ int warp_sums[32];
    int t = threadIdx.x;
    int base = t*10;
    int loc[10];
    int sum = 0;
    #pragma unroll
    for (int j = 0; j < 10; j++){
        int i = base + j;
        int v = (i < 10016) ? g_deg[i] : 0;
        loc[j] = sum; sum += v;
    }
    int lane = t & 31, w = t >> 5;
    int incl = sum;
    #pragma unroll
    for (int o = 1; o < 32; o <<= 1){
        int v = __shfl_up_sync(0xffffffffu, incl, o);
        if (lane >= o) incl += v;
    }
    if (lane == 31) warp_sums[w] = incl;
    __syncthreads();
    if (w == 0){
        int ws = warp_sums[lane];
        #pragma unroll
        for (int o = 1; o < 32; o <<= 1){
            int v = __shfl_up_sync(0xffffffffu, ws, o);
            if (lane >= o) ws += v;
        }
        warp_sums[lane] = ws;
    }
    __syncthreads();
    int offset = incl - sum + ((w > 0) ? warp_sums[w-1] : 0);
    #pragma unroll
    for (int j = 0; j < 10; j++){
        int i = base + j;
        if (i < 10016){ int o = offset + loc[j]; g_off[i] = o; g_cur[i] = o; }
    }
    if (t == 1023) g_off[10016] = offset + sum;
}
__global__ void scatter_kernel(const int* __restrict__ ei){
    int e = blockIdx.x*blockDim.x + threadIdx.x;
    if (e < N_EDGES){
        int n = ei[e];
        int p = atomicAdd(&g_cur[n], 1);
        g_elist[p] = e;
    }
}
__global__ void __launch_bounds__(1024) agg_kernel(){
    int z = blockIdx.x*blockDim.x + threadIdx.x;
    if (z < 10016) g_deg[z] = 0;
    int wid = threadIdx.x >> 5, lane = threadIdx.x & 31;
    int n = blockIdx.x*32 + wid;
    if (n >= N_NODES) return;
    int o0 = g_off[n], o1 = g_off[n+1];
    float4 acc = make_float4(0.f, 0.f, 0.f, 0.f);
    for (int i = o0; i < o1; i++){
        int e0 = g_elist[i];
        uint2 w = *(const uint2*)(g_m_bf + (size_t)e0*64 + lane*2);
        acc.x += bflo(w.x); acc.y += bfhi(w.x);
        acc.z += bflo(w.y); acc.w += bfhi(w.y);
    }
    int deg = o1 - o0;
    float s = (deg > 0) ? 1.0f/(float)deg : 1.0f;
    float4 o;
    o.x = acc.x*s; o.y = acc.y*s; o.z = acc.z*s; o.w = acc.w*s;
    *(float4*)(g_agg + (size_t)n*HID + lane*4) = o;
}

// ============ MMA core: 128x128 tile, 8 warps (2x4), warp tile 64x32 ============
#define MMA_TILE_G(tA, tB, MMAOP) do { \
    _Pragma("unroll") \
    for (int k0 = 0; k0 < 32; k0 += 8){ \
        uint32_t a[4][4]; \
        _Pragma("unroll") \
        for (int mt = 0; mt < 4; mt++){ \
            int R0 = wm + mt*16 + lr; \
            a[mt][0] = (tA)[swzi(R0,     k0 + lc)]; \
            a[mt][1] = (tA)[swzi(R0 + 8, k0 + lc)]; \
            a[mt][2] = (tA)[swzi(R0,     k0 + 4 + lc)]; \
            a[mt][3] = (tA)[swzi(R0 + 8, k0 + 4 + lc)]; \
        } \
        _Pragma("unroll") \
        for (int nt = 0; nt < 4; nt++){ \
            int n = wn + nt*8 + lr; \
            uint32_t b0 = (tB)[swzi(n, k0 + lc)]; \
            uint32_t b1 = (tB)[swzi(n, k0 + 4 + lc)]; \
            _Pragma("unroll") \
            for (int mt = 0; mt < 4; mt++) MMAOP(acc[mt][nt], a[mt], b0, b1); \
        } \
    } \
} while(0)
#define ACC_ZERO4() do { \
    _Pragma("unroll") \
    for (int i = 0; i < 4; i++) \
        _Pragma("unroll") \
        for (int j = 0; j < 4; j++){ acc[i][j][0]=0; acc[i][j][1]=0; acc[i][j][2]=0; acc[i][j][3]=0; } \
} while(0)

// -------- pre: P = xh @ [Wi | Wj]  (grid: 79 x 2, tf32) --------
__global__ void __launch_bounds__(256, 2) pre_P_mma(){
    extern __shared__ uint32_t dynsm[];
    const int tid = threadIdx.x;
    const int r0  = blockIdx.x*128;
    const int nb  = blockIdx.y;
    const uint32_t sbase = smem_u32(dynsm);
    const int lane = tid & 31, lr = lane >> 2, lc = lane & 3;
    const int wid = tid >> 5;
    const int wm = (wid & 1)*64, wn = (wid >> 1)*32;
    float acc[4][4][4];
    ACC_ZERO4();
    const int lr8 = tid >> 3, lc8 = tid & 7;

    #define ISSUE_P(st, kt) do { \
        uint32_t ab = sbase + OFF_A(st)*4u; \
        uint32_t bb = sbase + OFF_B(st)*4u; \
        _Pragma("unroll") \
        for (int i = 0; i < 4; i++){ \
            int r = lr8 + i*32, c = lc8; \
            int kg = (kt) + c*4; \
            uint32_t off = (uint32_t)(r*32 + (((c ^ r) & 7) << 2))*4u; \
            CP_ASYNC16(ab + off, (const void*)(g_xh + (size_t)(r0 + r)*HID + kg)); \
            CP_ASYNC16(bb + off, (const void*)(g_WijT + (size_t)(nb*128 + r)*HID + kg)); \
        } \
        CP_COMMIT(); \
    } while(0)

    ISSUE_P(0, 0);
    ISSUE_P(1, 32);
    int st = 0;
    for (int t = 0; t < 4; t++){
        if (t + 1 < 4) CP_WAIT(1); else CP_WAIT(0);
        __syncthreads();
        if (t + 2 < 4){
            int s2 = st + 2; if (s2 >= NSTAGE) s2 -= NSTAGE;
            ISSUE_P(s2, (t+2)*32);
        }
        MMA_TILE_G(dynsm + OFF_A(st), dynsm + OFF_B(st), mma8);
        if (++st == NSTAGE) st = 0;
    }
    #undef ISSUE_P
    #pragma unroll
    for (int mt = 0; mt < 4; mt++){
        int r1 = r0 + wm + mt*16 + lr;
        #pragma unroll
        for (int nt = 0; nt < 4; nt++){
            int c = wn + nt*8 + lc*2;
            float2 v1, v2;
            v1.x = acc[mt][nt][0]; v1.y = acc[mt][nt][1];
            v2.x = acc[mt][nt][2]; v2.y = acc[mt][nt][3];
            *(float2*)(g_P + (size_t)r1*256 + nb*128 + c) = v1;
            *(float2*)(g_P + (size_t)(r1+8)*256 + nb*128 + c) = v2;
        }
    }
}

// -------- FUSED edge kernel: phase A tf32 (w@Ww + P gathers) -> m1 bf16 in smem;
//          phase B bf16 (m1@We2, attention, gating) -> g_m_bf --------
__global__ void __launch_bounds__(256, 2) edge_fused_mma(const float* __restrict__ be1,
                                                         const float* __restrict__ be2,
                                                         const float* __restrict__ Wa,
                                                         const float* __restrict__ ba,
                                                         const float* __restrict__ weight,
                                                         const int* __restrict__ ei){
    extern __shared__ uint32_t dynsm[];   // A0 A1 B0 B1 M1a M1b (4096 words each)
    __shared__ float sB1[128], sB2[128], sWa[128], s_att[128];
    __shared__ int s_ii[128], s_jj[128];
    const int tid = threadIdx.x;
    const int e0  = blockIdx.x*128;
    if (tid < 128){
        s_ii[tid] = ei[e0 + tid];
        s_jj[tid] = ei[N_EDGES + e0 + tid];
        sB1[tid] = be1[tid];
        sB2[tid] = be2[tid];
        sWa[tid] = Wa[tid];
        s_att[tid] = 0.0f;
    }
    __syncthreads();
    const uint32_t sbase = smem_u32(dynsm);
    const int lane = tid & 31, lr = lane >> 2, lc = lane & 3;
    const int wid = tid >> 5;
    const int wm = (wid & 1)*64, wn = (wid >> 1)*32;
    float acc[4][4][4];
    ACC_ZERO4();
    const int lr8 = tid >> 3, lc8 = tid & 7;

    // ---- phase A: 13 tf32 K-tiles over [weight | WwT], 2-stage ----
    #define ISSUE_F(st, t) do { \
        uint32_t ab = sbase + (st)*(STG_WORDS*4u); \
        uint32_t bb = sbase + (2 + (st))*(STG_WORDS*4u); \
        _Pragma("unroll") \
        for (int i = 0; i < 4; i++){ \
            int r = lr8 + i*32, c = lc8; \
            int kg = (t)*32 + c*4; \
            uint32_t off = (uint32_t)(r*32 + (((c ^ r) & 7) << 2))*4u; \
            CP_ASYNC16(ab + off, (const void*)(weight + (size_t)(e0 + r)*EDIM + kg)); \
            CP_ASYNC16(bb + off, (const void*)(g_WwT + (size_t)r*EDIM + kg)); \
        } \
        CP_COMMIT(); \
    } while(0)

    ISSUE_F(0, 0);
    for (int t = 0; t < 13; t++){
        CP_WAIT(0);
        __syncthreads();
        if (t + 1 < 13) ISSUE_F((t+1)&1, t+1);
        MMA_TILE_G(dynsm + (t&1)*STG_WORDS, dynsm + (2 + (t&1))*STG_WORDS, mma8);
    }
    #undef ISSUE_F
    __syncthreads();   // all warps done with A/B stage buffers

    // stage We2 (bf16, 2 tiles) into B0/B1 while computing the phase-A epilogue
    #pragma unroll
    for (int tt = 0; tt < 2; tt++){
        #pragma unroll
        for (int i = 0; i < 4; i++){
            int r = lr8 + i*32, c = lc8;
            uint32_t off = (uint32_t)(r*32 + (((c ^ r) & 7) << 2))*4u;
            CP_ASYNC16(sbase + (2 + tt)*(STG_WORDS*4u) + off,
                       (const void*)(g_We2T_bf + (size_t)r*64 + tt*32 + c*4));
        }
    }
    CP_COMMIT();

    // phase-A epilogue: m1 = silu(acc + P_i + P_j + be1) -> M1 smem (bf16x2, swizzled)
    #pragma unroll
    for (int mt = 0; mt < 4; mt++){
        int r1 = wm + mt*16 + lr, r2 = r1 + 8;
        const float* P1i = g_P + (size_t)s_ii[r1]*256;
        const float* P1j = g_P + (size_t)s_jj[r1]*256 + 128;
        const float* P2i = g_P + (size_t)s_ii[r2]*256;
        const float* P2j = g_P + (size_t)s_jj[r2]*256 + 128;
        #pragma unroll
        for (int nt = 0; nt < 4; nt++){
            int c = wn + nt*8 + lc*2;
            float2 p1i = *(const float2*)(P1i + c), p1j = *(const float2*)(P1j + c);
            float2 p2i = *(const float2*)(P2i + c), p2j = *(const float2*)(P2j + c);
            float a0 = silu_f(acc[mt][nt][0] + p1i.x + p1j.x + sB1[c]);
            float a1 = silu_f(acc[mt][nt][1] + p1i.y + p1j.y + sB1[c+1]);
            float a2 = silu_f(acc[mt][nt][2] + p2i.x + p2j.x + sB1[c]);
            float a3 = silu_f(acc[mt][nt][3] + p2i.y + p2j.y + sB1[c+1]);
            int kb = c >> 6, kw = (c & 63) >> 1;
            dynsm[(4 + kb)*STG_WORDS + swzi(r1, kw)] = packbf(a0, a1);
            dynsm[(4 + kb)*STG_WORDS + swzi(r2, kw)] = packbf(a2, a3);
        }
    }
    CP_WAIT(0);
    __syncthreads();   // M1 visible + We2 staged

    // ---- phase B: m2 = m1 @ We2 (2 bf16 tiles from smem) ----
    ACC_ZERO4();
    MMA_TILE_G(dynsm + 4*STG_WORDS, dynsm + 2*STG_WORDS, mma16);
    MMA_TILE_G(dynsm + 5*STG_WORDS, dynsm + 3*STG_WORDS, mma16);

    // attention + gating epilogue
    #pragma unroll
    for (int mt = 0; mt < 4; mt++){
        float p0 = 0.0f, p1 = 0.0f;
        #pragma unroll
        for (int nt = 0; nt < 4; nt++){
            int c = wn + nt*8 + lc*2;
            float wa0 = sWa[c], wa1 = sWa[c+1];
            float v0 = silu_f(acc[mt][nt][0] + sB2[c]);
            float v1 = silu_f(acc[mt][nt][1] + sB2[c+1]);
            float v2 = silu_f(acc[mt][nt][2] + sB2[c]);
            float v3 = silu_f(acc[mt][nt][3] + sB2[c+1]);
            acc[mt][nt][0]=v0; acc[mt][nt][1]=v1; acc[mt][nt][2]=v2; acc[mt][nt][3]=v3;
            p0 += v0*wa0 + v1*wa1;
            p1 += v2*wa0 + v3*wa1;
        }
        atomicAdd(&s_att[wm + mt*16 + lr], p0);
        atomicAdd(&s_att[wm + mt*16 + lr + 8], p1);
    }
    __syncthreads();
    const float ba0 = ba[0];
    #pragma unroll
    for (int mt = 0; mt < 4; mt++){
        int r1 = wm + mt*16 + lr, r2 = r1 + 8;
        float att1 = silu_f(s_att[r1] + ba0);
        float att2 = silu_f(s_att[r2] + ba0);
        #pragma unroll
        for (int nt = 0; nt < 4; nt++){
            int c = wn + nt*8 + lc*2;
            g_m_bf[(size_t)(e0 + r1)*64 + (c >> 1)] = packbf(acc[mt][nt][0]*att1, acc[mt][nt][1]*att1);
            g_m_bf[(size_t)(e0 + r2)*64 + (c >> 1)] = packbf(acc[mt][nt][2]*att2, acc[mt][nt][3]*att2);
        }
    }
}

// -------- edge out (bf16): resident A (2 tiles) + 4 N-blocks x 2 K-tiles --------
__global__ void __launch_bounds__(256, 2) edge_out_mma(const float* __restrict__ bo,
                                                       const float* __restrict__ weight,
                                                       float* __restrict__ out){
    extern __shared__ uint32_t dynsm[];
    __shared__ float sBias[512];
    const int tid = threadIdx.x;
    const int e0  = blockIdx.x*128;
    sBias[tid] = (tid < EDIM) ? bo[tid] : 0.0f;
    sBias[tid+256] = (tid+256 < EDIM) ? bo[tid+256] : 0.0f;
    __syncthreads();
    const uint32_t sbase = smem_u32(dynsm);
    const int lane = tid & 31, lr = lane >> 2, lc = lane & 3;
    const int wid = tid >> 5;
    const int wm = (wid & 1)*64, wn = (wid >> 1)*32;
    float acc[4][4][4];
    const int lr8 = tid >> 3, lc8 = tid & 7;

    #pragma unroll
    for (int kb = 0; kb < 2; kb++){
        #pragma unroll
        for (int i = 0; i < 4; i++){
            int r = lr8 + i*32, c = lc8;
            uint32_t off = (uint32_t)(kb*STG_WORDS + r*32 + (((c ^ r) & 7) << 2))*4u;
            CP_ASYNC16(sbase + off, (const void*)(g_m_bf + (size_t)(e0 + r)*64 + kb*32 + c*4));
        }
    }
    CP_COMMIT();

    #define ISSUE_EO(st, idx) do { \
        int nb_ = (idx) >> 1, kt_ = (idx) & 1; \
        uint32_t bb = sbase + (2 + (st))*(STG_WORDS*4u); \
        _Pragma("unroll") \
        for (int i = 0; i < 4; i++){ \
            int r = lr8 + i*32, c = lc8; \
            uint32_t off = (uint32_t)(r*32 + (((c ^ r) & 7) << 2))*4u; \
            CP_ASYNC16(bb + off, (const void*)(g_WoT_bf + (size_t)(nb_*128 + r)*64 + kt_*32 + c*4)); \
        } \
        CP_COMMIT(); \
    } while(0)

    ISSUE_EO(0, 0);
    for (int idx = 0; idx < 8; idx++){
        int nb = idx >> 1, kt = idx & 1;
        if (kt == 0) ACC_ZERO4();
        CP_WAIT(0);
        __syncthreads();
        if (idx + 1 < 8) ISSUE_EO((idx+1)&1, idx+1);
        MMA_TILE_G(dynsm + kt*STG_WORDS, dynsm + (2 + (idx&1))*STG_WORDS, mma16);
        if (kt == 1){
            #pragma unroll
            for (int mt = 0; mt < 4; mt++){
                int r1 = e0 + wm + mt*16 + lr;
                #pragma unroll
                for (int nt = 0; nt < 4; nt++){
                    int c = wn + nt*8 + lc*2;
                    int g = nb*128 + c;
                    if (g < EDIM){
                        float2 w1 = *(const float2*)(weight + (size_t)r1*EDIM + g);
                        float2 w2 = *(const float2*)(weight + (size_t)(r1+8)*EDIM + g);
                        float2 v1, v2;
                        v1.x = w1.x + silu_f(acc[mt][nt][0] + sBias[g]);
                        v1.y = w1.y + silu_f(acc[mt][nt][1] + sBias[g+1]);
                        v2.x = w2.x + silu_f(acc[mt][nt][2] + sBias[g]);
                        v2.y = w2.y + silu_f(acc[mt][nt][3] + sBias[g+1]);
                        *(float2*)(out + X_OUT_ELEMS + (size_t)r1*EDIM + g) = v1;
                        *(float2*)(out + X_OUT_ELEMS + (size_t)(r1+8)*EDIM + g) = v2;
                    }
                }
            }
        }
    }
    #undef ISSUE_EO
}

// -------- node MLP 1 (tf32) --------
__global__ void __launch_bounds__(256, 2) node_mlp1_mma(const float* __restrict__ bn1){
    extern __shared__ uint32_t dynsm[];
    __shared__ float sBias[128];
    const int tid = threadIdx.x;
    const int r0  = blockIdx.x*128;
    if (tid < 128) sBias[tid] = bn1[tid];
    __syncthreads();
    const uint32_t sbase = smem_u32(dynsm);
    const int lane = tid & 31, lr = lane >> 2, lc = lane & 3;
    const int wid = tid >> 5;
    const int wm = (wid & 1)*64, wn = (wid >> 1)*32;
    float acc[4][4][4];
    ACC_ZERO4();
    const int lr8 = tid >> 3, lc8 = tid & 7;

    #define ISSUE_N1(st, kt) do { \
        uint32_t ab = sbase + OFF_A(st)*4u; \
        uint32_t bb = sbase + OFF_B(st)*4u; \
        _Pragma("unroll") \
        for (int i = 0; i < 4; i++){ \
            int r = lr8 + i*32, c = lc8; \
            int kg = (kt) + c*4; \
            const void* srcA = (kg < HID) ? (const void*)(g_xh + (size_t)(r0 + r)*HID + kg) \
                                          : (const void*)(g_agg + (size_t)(r0 + r)*HID + (kg - HID)); \
            uint32_t off = (uint32_t)(r*32 + (((c ^ r) & 7) << 2))*4u; \
            CP_ASYNC16(ab + off, srcA); \
            CP_ASYNC16(bb + off, (const void*)(g_WnT1 + (size_t)r*256 + kg)); \
        } \
        CP_COMMIT(); \
    } while(0)

    ISSUE_N1(0, 0);
    ISSUE_N1(1, 32);
    int st = 0;
    for (int t = 0; t < 8; t++){
        if (t + 1 < 8) CP_WAIT(1); else CP_WAIT(0);
        __syncthreads();
        if (t + 2 < 8){
            int s2 = st + 2; if (s2 >= NSTAGE) s2 -= NSTAGE;
            ISSUE_N1(s2, (t+2)*32);
        }
        MMA_TILE_G(dynsm + OFF_A(st), dynsm + OFF_B(st), mma8);
        if (++st == NSTAGE) st = 0;
    }
    #undef ISSUE_N1
    #pragma unroll
    for (int mt = 0; mt < 4; mt++){
        int r1 = r0 + wm + mt*16 + lr;
        #pragma unroll
        for (int nt = 0; nt < 4; nt++){
            int c = wn + nt*8 + lc*2;
            float2 v1, v2;
            v1.x = silu_f(acc[mt][nt][0] + sBias[c]);
            v1.y = silu_f(acc[mt][nt][1] + sBias[c+1]);
            v2.x = silu_f(acc[mt][nt][2] + sBias[c]);
            v2.y = silu_f(acc[mt][nt][3] + sBias[c+1]);
            *(float2*)(g_n1 + (size_t)r1*HID + c) = v1;
            *(float2*)(g_n1 + (size_t)(r1+8)*HID + c) = v2;
        }
    }
}

// -------- node MLP 2 (tf32) + residual --------
__global__ void __launch_bounds__(256, 2) node_mlp2_mma(const float* __restrict__ bn2,
                                                        float* __restrict__ out){
    extern __shared__ uint32_t dynsm[];
    __shared__ float sBias[128];
    const int tid = threadIdx.x;
    const int r0  = blockIdx.x*128;
    if (tid < 128) sBias[tid] = bn2[tid];
    __syncthreads();
    const uint32_t sbase = smem_u32(dynsm);
    const int lane = tid & 31, lr = lane >> 2, lc = lane & 3;
    const int wid = tid >> 5;
    const int wm = (wid & 1)*64, wn = (wid >> 1)*32;
    float acc[4][4][4];
    ACC_ZERO4();
    const int lr8 = tid >> 3, lc8 = tid & 7;

    #define ISSUE_N2(st, kt) do { \
        uint32_t ab = sbase + OFF_A(st)*4u; \
        uint32_t bb = sbase + OFF_B(st)*4u; \
        _Pragma("unroll") \
        for (int i = 0; i < 4; i++){ \
            int r = lr8 + i*32, c = lc8; \
            int kg = (kt) + c*4; \
            uint32_t off = (uint32_t)(r*32 + (((c ^ r) & 7) << 2))*4u; \
            CP_ASYNC16(ab + off, (const void*)(g_n1 + (size_t)(r0 + r)*HID + kg)); \
            CP_ASYNC16(bb + off, (const void*)(g_Wn2T + (size_t)r*HID + kg)); \
        } \
        CP_COMMIT(); \
    } while(0)

    ISSUE_N2(0, 0);
    ISSUE_N2(1, 32);
    int st = 0;
    for (int t = 0; t < 4; t++){
        if (t + 1 < 4) CP_WAIT(1); else CP_WAIT(0);
        __syncthreads();
        if (t + 2 < 4){
            int s2 = st + 2; if (s2 >= NSTAGE) s2 -= NSTAGE;
            ISSUE_N2(s2, (t+2)*32);
        }
        MMA_TILE_G(dynsm + OFF_A(st), dynsm + OFF_B(st), mma8);
        if (++st == NSTAGE) st = 0;
    }
    #undef ISSUE_N2
    #pragma unroll
    for (int mt = 0; mt < 4; mt++){
        int r1 = r0 + wm + mt*16 + lr;
        #pragma unroll
        for (int nt = 0; nt < 4; nt++){
            int c = wn + nt*8 + lc*2;
            if (r1 < N_NODES){
                float2 xh1 = *(const float2*)(g_xh + (size_t)r1*HID + c);
                float2 v1;
                v1.x = xh1.x + silu_f(acc[mt][nt][0] + sBias[c]);
                v1.y = xh1.y + silu_f(acc[mt][nt][1] + sBias[c+1]);
                *(float2*)(out + (size_t)r1*HID + c) = v1;
            }
            if (r1 + 8 < N_NODES){
                float2 xh2 = *(const float2*)(g_xh + (size_t)(r1+8)*HID + c);
                float2 v2;
                v2.x = xh2.x + silu_f(acc[mt][nt][2] + sBias[c]);
                v2.y = xh2.y + silu_f(acc[mt][nt][3] + sBias[c+1]);
                *(float2*)(out + (size_t)(r1+8)*HID + c) = v2;
            }
        }
    }
}

extern "C" void kernel_launch(void* const* d_in, const int* in_sizes, int n_in,
                              void* d_out, int out_size){
    const float* x    = (const float*)d_in[0];
    const float* wgt  = (const float*)d_in[1];
    const float* ln_g = (const float*)d_in[2];
    const float* ln_b = (const float*)d_in[3];
    const float* We1  = (const float*)d_in[4];
    const float* be1  = (const float*)d_in[5];
    const float* We2  = (const float*)d_in[6];
    const float* be2  = (const float*)d_in[7];
    const float* Wa   = (const float*)d_in[8];
    const float* ba   = (const float*)d_in[9];
    const float* Wn1  = (const float*)d_in[10];
    const float* bn1  = (const float*)d_in[11];
    const float* Wn2  = (const float*)d_in[12];
    const float* bn2  = (const float*)d_in[13];
    const float* Wo   = (const float*)d_in[14];
    const float* bo   = (const float*)d_in[15];
    const int*   ei   = (const int*)d_in[16];
    float* out = (float*)d_out;

    cudaFuncSetAttribute(pre_P_mma,      cudaFuncAttributeMaxDynamicSharedMemorySize, SMEM_STD);
    cudaFuncSetAttribute(edge_fused_mma, cudaFuncAttributeMaxDynamicSharedMemorySize, SMEM_FUSED);
    cudaFuncSetAttribute(edge_out_mma,   cudaFuncAttributeMaxDynamicSharedMemorySize, SMEM_BF);
    cudaFuncSetAttribute(node_mlp1_mma,  cudaFuncAttributeMaxDynamicSharedMemorySize, SMEM_STD);
    cudaFuncSetAttribute(node_mlp2_mma,  cudaFuncAttributeMaxDynamicSharedMemorySize, SMEM_STD);

    cudaStream_t s1;
    cudaStreamCreateWithFlags(&s1, cudaStreamNonBlocking);
    cudaEvent_t evFork, evM, evJoin;
    cudaEventCreateWithFlags(&evFork, cudaEventDisableTiming);
    cudaEventCreateWithFlags(&evM,    cudaEventDisableTiming);
    cudaEventCreateWithFlags(&evJoin, cudaEventDisableTiming);

    cudaEventRecord(evFork, 0);

    // main chain (edge_fused in the profiled 4th slot)
    setup_kernel<<<(65536 + 255)/256, 256>>>(We1, We2, Wo, Wn1, Wn2);
    ln_kernel<<<(N_NODES + 7)/8, dim3(32, 8)>>>(x, ln_g, ln_b);
    pre_P_mma<<<dim3(NODES_PAD/128, 2), 256, SMEM_STD>>>();
    edge_fused_mma<<<N_EDGES/128, 256, SMEM_FUSED>>>(be1, be2, Wa, ba, wgt, ei);

    // side chain: CSR build (concurrent with the above)
    cudaStreamWaitEvent(s1, evFork, 0);
    hist_kernel<<<(N_EDGES + 255)/256, 256, 0, s1>>>(ei);
    scan_kernel<<<1, 1024, 0, s1>>>();
    scatter_kernel<<<(N_EDGES + 255)/256, 256, 0, s1>>>(ei);

    cudaEventRecord(evM, 0);                    // m_ij ready

    // side chain: node pipeline (concurrent with edge_out)
    cudaStreamWaitEvent(s1, evM, 0);
    agg_kernel<<<(N_NODES + 31)/32, 1024, 0, s1>>>();
    node_mlp1_mma<<<NODES_PAD/128, 256, SMEM_STD, s1>>>(bn1);
    node_mlp2_mma<<<NODES_PAD/128, 256, SMEM_STD, s1>>>(bn2, out);
    cudaEventRecord(evJoin, s1);

    // main chain: edge output transform
    edge_out_mma<<<N_EDGES/128, 256, SMEM_BF>>>(bo, wgt, out);
    cudaStreamWaitEvent(0, evJoin, 0);
}